// round 11
// baseline (speedup 1.0000x reference)
#include <cuda_runtime.h>
#include <cuda_fp16.h>
#include <math.h>
#include <stdint.h>

// ---------------- problem constants ----------------
#define BATCH 2048
#define SIZE_D 2048
#define HID 1024
#define NC 17
#define OUTW (SIZE_D * NC)   // 34816
#define NTOT (BATCH * SIZE_D)
#define EPS_C 1e-6f
#define NSTATBLK (NTOT / 4 / 256)   // 4096

// ---------------- GEMM tiling ----------------
#define GBM 128
#define GBK 32
#define GSTAGES 5
#define TILE_A_BYTES 8192                       // 128 rows x 64B

// ---------------- device scratch ----------------
__device__ __half g_xh[(size_t)NTOT];
__device__ __half g_w1t[(size_t)HID * SIZE_D];
__device__ __half g_h[(size_t)BATCH * HID];
__device__ __half g_w2t[(size_t)OUTW * HID];
__device__ __half g_net[(size_t)BATCH * OUTW];
__device__ float g_colsum[HID];
__device__ float g_part_s[NSTATBLK];
__device__ float g_part_ss[NSTATBLK];
__device__ float g_stats[2];
__device__ unsigned int g_ctr;   // zero-initialized; reset by last block each run

// ---------------- PTX helpers ----------------
__device__ __forceinline__ uint32_t smem_u32(const void* p) {
    uint32_t a;
    asm("{ .reg .u64 t; cvta.to.shared.u64 t, %1; cvt.u32.u64 %0, t; }"
        : "=r"(a) : "l"(p));
    return a;
}
__device__ __forceinline__ void cp_async16(uint32_t sa, const void* ga) {
    asm volatile("cp.async.cg.shared.global [%0], [%1], 16;"
                 :: "r"(sa), "l"(ga) : "memory");
}
__device__ __forceinline__ void cp_commit() {
    asm volatile("cp.async.commit_group;" ::: "memory");
}
template <int N>
__device__ __forceinline__ void cp_wait() {
    asm volatile("cp.async.wait_group %0;" :: "n"(N) : "memory");
}
__device__ __forceinline__ void ldmatrix_x4(uint32_t* r, uint32_t addr) {
    asm volatile("ldmatrix.sync.aligned.m8n8.x4.shared.b16 {%0,%1,%2,%3}, [%4];"
                 : "=r"(r[0]), "=r"(r[1]), "=r"(r[2]), "=r"(r[3])
                 : "r"(addr));
}
__device__ __forceinline__ void mma16816(float* c, const uint32_t* a,
                                         uint32_t b0, uint32_t b1) {
    asm volatile(
        "mma.sync.aligned.m16n8k16.row.col.f32.f16.f16.f32 "
        "{%0,%1,%2,%3}, {%4,%5,%6,%7}, {%8,%9}, {%0,%1,%2,%3};"
        : "+f"(c[0]), "+f"(c[1]), "+f"(c[2]), "+f"(c[3])
        : "r"(a[0]), "r"(a[1]), "r"(a[2]), "r"(a[3]), "r"(b0), "r"(b1));
}
__device__ __forceinline__ uint32_t sw_off(int row, int ch) {
    return ((uint32_t)row << 6) + (((ch ^ (row >> 1)) & 3) << 4);
}
__device__ __forceinline__ float fast_tanh(float x) {
    float e = __expf(2.0f * x);
    return 1.0f - 2.0f / (e + 1.0f);
}

// ---------------- prep kernel: stats + x fp16 + logd copy + colsum zero ----
// Fused finalize via last-block-done pattern (threadFenceReduction style).
__global__ __launch_bounds__(256)
void stat_split(const float* __restrict__ xp, __half* __restrict__ xh,
                const float* __restrict__ logd, float* __restrict__ log_out) {
    const int i = blockIdx.x * blockDim.x + threadIdx.x;
    const int tid = threadIdx.x;
    float4 v = ((const float4*)xp)[i];

    __half2 p0 = {__float2half_rn(v.x), __float2half_rn(v.y)};
    __half2 p1 = {__float2half_rn(v.z), __float2half_rn(v.w)};
    uint2 hv = {*(uint32_t*)&p0, *(uint32_t*)&p1};
    ((uint2*)xh)[i] = hv;

    if (blockIdx.x == 0) {
#pragma unroll
        for (int c = 0; c < HID / 256; c++)
            g_colsum[tid + c * 256] = 0.f;
    }
    // init log_out with logd (2048 values, blocks 0..7)
    if (blockIdx.x < 8)
        log_out[blockIdx.x * 256 + tid] = logd[blockIdx.x * 256 + tid];

    float s = v.x + v.y + v.z + v.w;
    float ss = v.x * v.x + v.y * v.y + v.z * v.z + v.w * v.w;
    __shared__ float shs[256];
    __shared__ float shss[256];
    __shared__ int slast;
    shs[tid] = s; shss[tid] = ss;
    __syncthreads();
    for (int o = 128; o > 0; o >>= 1) {
        if (tid < o) { shs[tid] += shs[tid + o]; shss[tid] += shss[tid + o]; }
        __syncthreads();
    }
    if (tid == 0) {
        g_part_s[blockIdx.x] = shs[0];
        g_part_ss[blockIdx.x] = shss[0];
        __threadfence();
        unsigned int old = atomicAdd(&g_ctr, 1u);
        slast = (old == gridDim.x - 1) ? 1 : 0;
    }
    __syncthreads();
    if (slast) {
        __threadfence();
        float fs = 0.f, fss = 0.f;
        for (int k = tid; k < NSTATBLK; k += 256) { fs += g_part_s[k]; fss += g_part_ss[k]; }
        shs[tid] = fs; shss[tid] = fss;
        __syncthreads();
        for (int o = 128; o > 0; o >>= 1) {
            if (tid < o) { shs[tid] += shs[tid + o]; shss[tid] += shss[tid + o]; }
            __syncthreads();
        }
        if (tid == 0) {
            float S = shs[0], SS = shss[0];
            float mean = S / (float)NTOT;
            float var = (SS - S * mean) / (float)(NTOT - 1);
            g_stats[0] = mean;
            g_stats[1] = rsqrtf(var);
            g_ctr = 0;   // reset for next graph replay
        }
    }
}

// ---------------- transpose -> fp16, 64x64 tiles, vectorized ----------------
template <int DOCOLSUM>
__global__ __launch_bounds__(256)
void transpose_half(const float* __restrict__ src,
                    __half* __restrict__ dst, int K, int N) {
    __shared__ float t[64][65];
    const int n0 = blockIdx.x * 64;
    const int k0 = blockIdx.y * 64;
    const int tid = threadIdx.x;

    const int lr = tid >> 4;
    const int lc = (tid & 15) * 4;
#pragma unroll
    for (int i = 0; i < 64; i += 16) {
        float4 v = *(const float4*)(src + (size_t)(k0 + lr + i) * N + n0 + lc);
        t[lr + i][lc + 0] = v.x;
        t[lr + i][lc + 1] = v.y;
        t[lr + i][lc + 2] = v.z;
        t[lr + i][lc + 3] = v.w;
    }
    __syncthreads();

    if (DOCOLSUM && tid < 64) {
        float s = 0.f;
#pragma unroll
        for (int r = 0; r < 64; r++) s += t[r][tid];
        atomicAdd(&g_colsum[n0 + tid], s);
    }

    const int wid = tid >> 5;
    const int lane = tid & 31;
#pragma unroll
    for (int i = 0; i < 64; i += 8) {
        const int r = wid + i;
        const int k = lane * 2;
        __half2 hp = {__float2half_rn(t[k][r]), __float2half_rn(t[k + 1][r])};
        *(__half2*)(dst + (size_t)(n0 + r) * K + k0 + k) = hp;
    }
}

// ---------------- plain fp16 GEMM, templated N-tile (NG n-groups/warp) ------
// Tile: 128 x (NG*32). NG=4 -> 128x128, NG=2 -> 128x64.
template <int EPI, int NG>
__global__ __launch_bounds__(256, 2)
void gemm_fp16(const __half* __restrict__ A,
               const __half* __restrict__ B,
               const float* __restrict__ bias,
               const float* __restrict__ colsum,
               __half* __restrict__ C,
               int K, int Nout, int KTILES) {
    constexpr int TILE_B_BYTES = NG * 2048;            // (NG*32) rows x 64B
    constexpr int STAGE_B = TILE_A_BYTES + TILE_B_BYTES;
    constexpr int GBN = NG * 32;

    extern __shared__ __align__(128) char smem[];
    const uint32_t sb = smem_u32(smem);
    const int tid = threadIdx.x;
    const int wid = tid >> 5;
    const int lane = tid & 31;
    const int wm = wid & 3;
    const int wn = wid >> 2;
    const int m0 = blockIdx.x * GBM;
    const int n0 = blockIdx.y * GBN;

    const int r0c = tid >> 2, c0c = tid & 3;
    const int r1c = (tid + 256) >> 2;

    float acc[2][2 * NG][4];
#pragma unroll
    for (int a = 0; a < 2; a++)
#pragma unroll
        for (int b = 0; b < 2 * NG; b++)
#pragma unroll
            for (int c = 0; c < 4; c++) acc[a][b][c] = 0.f;

    auto load_stage = [&](int s, int kt) {
        const uint32_t base = sb + s * STAGE_B;
        const size_t kof = (size_t)kt * GBK;
        {
            uint32_t so = sw_off(r0c, c0c);
            cp_async16(base + so, A + (size_t)(m0 + r0c) * K + kof + c0c * 8);
            cp_async16(base + TILE_A_BYTES + so,
                       B + (size_t)(n0 + r0c) * K + kof + c0c * 8);
        }
        {
            uint32_t so = sw_off(r1c, c0c);
            cp_async16(base + so, A + (size_t)(m0 + r1c) * K + kof + c0c * 8);
            if (NG == 4)
                cp_async16(base + TILE_A_BYTES + so,
                           B + (size_t)(n0 + r1c) * K + kof + c0c * 8);
        }
    };

#pragma unroll
    for (int s = 0; s < GSTAGES - 1; s++) {
        load_stage(s, s);
        cp_commit();
    }

    const int lrow = lane & 15;
    const int lhalf = lane >> 4;

    int cs = 0;
    int ls = GSTAGES - 1;
    for (int kt = 0; kt < KTILES; kt++) {
        cp_wait<GSTAGES - 2>();
        __syncthreads();

        const int nk = kt + GSTAGES - 1;
        if (nk < KTILES) load_stage(ls, nk);
        cp_commit();

        const uint32_t sA = sb + cs * STAGE_B;
        const uint32_t sB = sA + TILE_A_BYTES;

#pragma unroll
        for (int k16 = 0; k16 < 2; k16++) {
            const int kc = k16 * 2 + lhalf;
            uint32_t afr[2][4];
#pragma unroll
            for (int mt = 0; mt < 2; mt++) {
                int row = wm * 32 + mt * 16 + lrow;
                ldmatrix_x4(afr[mt], sA + sw_off(row, kc));
            }
#pragma unroll
            for (int g = 0; g < NG; g++) {
                int row = wn * (NG * 16) + g * 16 + lrow;
                uint32_t bfr[4];
                ldmatrix_x4(bfr, sB + sw_off(row, kc));
#pragma unroll
                for (int mt = 0; mt < 2; mt++) {
#pragma unroll
                    for (int p = 0; p < 2; p++) {
                        mma16816(acc[mt][g * 2 + p], afr[mt], bfr[p], bfr[2 + p]);
                    }
                }
            }
        }
        cs = (cs + 1 == GSTAGES) ? 0 : cs + 1;
        ls = (ls + 1 == GSTAGES) ? 0 : ls + 1;
    }

    // ---------------- epilogue ----------------
    float mean = 0.f, invstd = 1.f;
    if (EPI == 0) { mean = g_stats[0]; invstd = g_stats[1]; }

    const int r_base = m0 + wm * 32 + (lane >> 2);
    const int c_base = n0 + wn * (NG * 16) + (lane & 3) * 2;

#pragma unroll
    for (int mt = 0; mt < 2; mt++) {
#pragma unroll
        for (int nf = 0; nf < 2 * NG; nf++) {
            const int col = c_base + nf * 8;
            float be0, be1;
            if (EPI == 0) {
                be0 = bias[col]     - mean * invstd * colsum[col];
                be1 = bias[col + 1] - mean * invstd * colsum[col + 1];
            } else {
                be0 = bias[col];
                be1 = bias[col + 1];
            }
#pragma unroll
            for (int hh = 0; hh < 2; hh++) {
                const int row = r_base + mt * 16 + hh * 8;
                float v0 = acc[mt][nf][hh * 2 + 0];
                float v1 = acc[mt][nf][hh * 2 + 1];
                if (EPI == 0) {
                    v0 = fast_tanh(fmaf(invstd, v0, be0));
                    v1 = fast_tanh(fmaf(invstd, v1, be1));
                } else {
                    v0 = fast_tanh(v0 + be0);
                    v1 = fast_tanh(v1 + be1);
                }
                __half2 hp = {__float2half_rn(v0), __float2half_rn(v1)};
                *(__half2*)(C + (size_t)row * Nout + col) = hp;
            }
        }
    }
}

// ---------------- spline: one 256-site chunk per block, atomic log-sum ------
__global__ __launch_bounds__(256)
void spline_kernel(const __half* __restrict__ net, const float* __restrict__ x_in,
                   float* __restrict__ phi_out, float* __restrict__ log_out) {
    const int bx = blockIdx.x;
    const int b = bx >> 3;
    const int chunk = bx & 7;
    const int tid = threadIdx.x;

    __shared__ float sh[256 * NC];
    __shared__ float red[256];

    const __half2* rowc =
        (const __half2*)(net + (size_t)b * OUTW + (size_t)chunk * 256 * NC);
    for (int i = tid; i < 128 * NC; i += 256) {
        float2 v = __half22float2(rowc[i]);
        sh[2 * i]     = v.x;
        sh[2 * i + 1] = v.y;
    }
    __syncthreads();

    const int s = chunk * 256 + tid;
    const float* p = sh + tid * NC;

    float hr[9], wr[8];
#pragma unroll
    for (int c = 0; c < 9; c++) hr[c] = p[c];
#pragma unroll
    for (int c = 0; c < 8; c++) wr[c] = p[9 + c];

    float m = wr[0];
#pragma unroll
    for (int c = 1; c < 8; c++) m = fmaxf(m, wr[c]);
    float wn[8];
    float wsum = 0.f;
#pragma unroll
    for (int c = 0; c < 8; c++) { wn[c] = __expf(wr[c] - m); wsum += wn[c]; }
    float winv = 1.0f / wsum;
#pragma unroll
    for (int c = 0; c < 8; c++) wn[c] *= winv;

    float eh[9];
#pragma unroll
    for (int c = 0; c < 9; c++) eh[c] = __expf(hr[c]);
    float denom = 0.f;
#pragma unroll
    for (int c = 0; c < 8; c++) denom += 0.5f * wn[c] * (eh[c] + eh[c + 1]);
    float dinv = 1.0f / denom;
    float hn[9];
#pragma unroll
    for (int c = 0; c < 9; c++) hn[c] = eh[c] * dinv;

    const float x = x_in[(size_t)b * SIZE_D + s] * 0.31830988618379067154f;

    float cum = 0.f, phicum = 0.f;
    float wk = wn[0], hk = hn[0], hk1 = hn[1];
    float xkm1 = -EPS_C, phikm1 = 0.f;
#pragma unroll
    for (int i = 0; i < 7; i++) {
        float trap = 0.5f * wn[i] * (hn[i] + hn[i + 1]);
        cum += wn[i];
        phicum += trap;
        bool c = (cum < x);
        wk     = c ? wn[i + 1] : wk;
        hk     = c ? hn[i + 1] : hk;
        hk1    = c ? hn[i + 2] : hk1;
        xkm1   = c ? cum      : xkm1;
        phikm1 = c ? phicum   : phikm1;
    }

    float alpha = (x - xkm1) / wk;
    float phi = phikm1 + alpha * hk * wk
              + 0.5f * alpha * alpha * (hk1 - hk) * wk;
    phi_out[(size_t)b * SIZE_D + s] = phi;

    red[tid] = __logf(hk + alpha * (hk1 - hk));
    __syncthreads();
    for (int o = 128; o > 0; o >>= 1) {
        if (tid < o) red[tid] += red[tid + o];
        __syncthreads();
    }
    if (tid == 0) atomicAdd(&log_out[b], -red[0]);
}

// ---------------- launch ----------------
extern "C" void kernel_launch(void* const* d_in, const int* in_sizes, int n_in,
                              void* d_out, int out_size) {
    (void)in_sizes; (void)n_in; (void)out_size;
    const float* x_in      = (const float*)d_in[0];
    const float* x_passive = (const float*)d_in[1];
    const float* log_dens  = (const float*)d_in[2];
    const float* w1        = (const float*)d_in[3];
    const float* b1        = (const float*)d_in[4];
    const float* w2        = (const float*)d_in[5];
    const float* b2        = (const float*)d_in[6];

    float* out_phi = (float*)d_out;
    float* out_log = (float*)d_out + (size_t)NTOT;

    __half *xh, *w1t, *hbuf, *w2t, *nbuf;
    float *csum;
    cudaGetSymbolAddress((void**)&xh, g_xh);
    cudaGetSymbolAddress((void**)&w1t, g_w1t);
    cudaGetSymbolAddress((void**)&hbuf, g_h);
    cudaGetSymbolAddress((void**)&w2t, g_w2t);
    cudaGetSymbolAddress((void**)&nbuf, g_net);
    cudaGetSymbolAddress((void**)&csum, g_colsum);

    const int SMEM1 = GSTAGES * (TILE_A_BYTES + 2 * 2048);  // NG=2: 61440
    const int SMEM2 = GSTAGES * (TILE_A_BYTES + 4 * 2048);  // NG=4: 81920
    cudaFuncSetAttribute((const void*)gemm_fp16<0, 2>,
                         cudaFuncAttributeMaxDynamicSharedMemorySize, SMEM1);
    cudaFuncSetAttribute((const void*)gemm_fp16<1, 4>,
                         cudaFuncAttributeMaxDynamicSharedMemorySize, SMEM2);

    // 0) w2 transpose (longest prep, independent) — first so ncu slot = gemm1
    transpose_half<0><<<dim3(OUTW / 64, HID / 64), 256>>>(w2, w2t, HID, OUTW);
    // 1) stats + x fp16 + logd init + colsum zero (fused finalize)
    stat_split<<<NSTATBLK, 256>>>(x_passive, xh, log_dens, out_log);
    // 2) w1 transpose + colsum accumulate
    transpose_half<1><<<dim3(HID / 64, SIZE_D / 64), 256>>>(w1, w1t, SIZE_D, HID);
    // 3) GEMM1: h = tanh(xs @ w1 + b1) -> fp16   (128x64 tiles, 256 CTAs)
    gemm_fp16<0, 2><<<dim3(BATCH / GBM, HID / 64), 256, SMEM1>>>(
        xh, w1t, b1, csum, hbuf, SIZE_D, HID, SIZE_D / GBK);
    // 4) GEMM2: net = tanh(h @ w2 + b2) -> fp16  (128x128 tiles)
    gemm_fp16<1, 4><<<dim3(BATCH / GBM, OUTW / 128), 256, SMEM2>>>(
        hbuf, w2t, b2, nullptr, nbuf, HID, OUTW, HID / GBK);
    // 5) spline: one chunk per block + per-row atomic log reduction
    spline_kernel<<<BATCH * 8, 256>>>(nbuf, x_in, out_phi, out_log);
}

// round 12
// speedup vs baseline: 1.0629x; 1.0629x over previous
#include <cuda_runtime.h>
#include <cuda_fp16.h>
#include <math.h>
#include <stdint.h>

// ---------------- problem constants ----------------
#define BATCH 2048
#define SIZE_D 2048
#define HID 1024
#define NC 17
#define OUTW (SIZE_D * NC)   // 34816
#define NTOT (BATCH * SIZE_D)
#define EPS_C 1e-6f
#define NSTATBLK (NTOT / 4 / 256)   // 4096
#define NW1TBLK ((HID / 64) * (SIZE_D / 64))   // 16*32 = 512

// ---------------- GEMM tiling ----------------
#define GBM 128
#define GBK 32
#define GSTAGES 5
#define TILE_A_BYTES 8192   // 128 rows x 64B

// ---------------- device scratch ----------------
__device__ __half g_xh[(size_t)NTOT];
__device__ __half g_w1t[(size_t)HID * SIZE_D];
__device__ __half g_h[(size_t)BATCH * HID];
__device__ __half g_w2t[(size_t)OUTW * HID];
__device__ __half g_net[(size_t)BATCH * OUTW];
__device__ float g_colsum[HID];          // zero at load; re-zeroed by spline each run
__device__ float g_part_s[NSTATBLK];
__device__ float g_part_ss[NSTATBLK];
__device__ float g_stats[2];
__device__ unsigned int g_ctr;           // zero at load; reset by finalize block

// ---------------- PTX helpers ----------------
__device__ __forceinline__ uint32_t smem_u32(const void* p) {
    uint32_t a;
    asm("{ .reg .u64 t; cvta.to.shared.u64 t, %1; cvt.u32.u64 %0, t; }"
        : "=r"(a) : "l"(p));
    return a;
}
__device__ __forceinline__ void cp_async16(uint32_t sa, const void* ga) {
    asm volatile("cp.async.cg.shared.global [%0], [%1], 16;"
                 :: "r"(sa), "l"(ga) : "memory");
}
__device__ __forceinline__ void cp_commit() {
    asm volatile("cp.async.commit_group;" ::: "memory");
}
template <int N>
__device__ __forceinline__ void cp_wait() {
    asm volatile("cp.async.wait_group %0;" :: "n"(N) : "memory");
}
__device__ __forceinline__ void ldmatrix_x4(uint32_t* r, uint32_t addr) {
    asm volatile("ldmatrix.sync.aligned.m8n8.x4.shared.b16 {%0,%1,%2,%3}, [%4];"
                 : "=r"(r[0]), "=r"(r[1]), "=r"(r[2]), "=r"(r[3])
                 : "r"(addr));
}
__device__ __forceinline__ void mma16816(float* c, const uint32_t* a,
                                         uint32_t b0, uint32_t b1) {
    asm volatile(
        "mma.sync.aligned.m16n8k16.row.col.f32.f16.f16.f32 "
        "{%0,%1,%2,%3}, {%4,%5,%6,%7}, {%8,%9}, {%0,%1,%2,%3};"
        : "+f"(c[0]), "+f"(c[1]), "+f"(c[2]), "+f"(c[3])
        : "r"(a[0]), "r"(a[1]), "r"(a[2]), "r"(a[3]), "r"(b0), "r"(b1));
}
__device__ __forceinline__ uint32_t sw_off(int row, int ch) {
    return ((uint32_t)row << 6) + (((ch ^ (row >> 1)) & 3) << 4);
}
__device__ __forceinline__ float fast_tanh(float x) {
    float e = __expf(2.0f * x);
    return 1.0f - 2.0f / (e + 1.0f);
}

// ---------------- fused prep: stats(+finalize) and w1 transpose+colsum ------
// Blocks [0, NSTATBLK): x stats partials + fp16 convert; last one finalizes.
// Blocks [NSTATBLK, NSTATBLK+NW1TBLK): w1 [K=2048][N=1024] -> w1t fp16 + colsum
// (colsum is zero at entry: zero-init at load, re-zeroed by spline each run).
__global__ __launch_bounds__(256)
void prep_fused(const float* __restrict__ xp, __half* __restrict__ xh,
                const float* __restrict__ w1, __half* __restrict__ w1t) {
    __shared__ float smembuf[64 * 65];
    __shared__ int slast;
    const int tid = threadIdx.x;

    if (blockIdx.x < NSTATBLK) {
        // ---- stats + x fp16 path ----
        const int i = blockIdx.x * 256 + tid;
        float4 v = ((const float4*)xp)[i];

        __half2 p0 = {__float2half_rn(v.x), __float2half_rn(v.y)};
        __half2 p1 = {__float2half_rn(v.z), __float2half_rn(v.w)};
        uint2 hv = {*(uint32_t*)&p0, *(uint32_t*)&p1};
        ((uint2*)xh)[i] = hv;

        float* shs = smembuf;
        float* shss = smembuf + 256;
        float s = v.x + v.y + v.z + v.w;
        float ss = v.x * v.x + v.y * v.y + v.z * v.z + v.w * v.w;
        shs[tid] = s; shss[tid] = ss;
        __syncthreads();
        for (int o = 128; o > 0; o >>= 1) {
            if (tid < o) { shs[tid] += shs[tid + o]; shss[tid] += shss[tid + o]; }
            __syncthreads();
        }
        if (tid == 0) {
            g_part_s[blockIdx.x] = shs[0];
            g_part_ss[blockIdx.x] = shss[0];
            __threadfence();
            unsigned int old = atomicAdd(&g_ctr, 1u);
            slast = (old == NSTATBLK - 1) ? 1 : 0;
        }
        __syncthreads();
        if (slast) {
            __threadfence();
            float fs = 0.f, fss = 0.f;
            for (int k = tid; k < NSTATBLK; k += 256) {
                fs += g_part_s[k]; fss += g_part_ss[k];
            }
            shs[tid] = fs; shss[tid] = fss;
            __syncthreads();
            for (int o = 128; o > 0; o >>= 1) {
                if (tid < o) { shs[tid] += shs[tid + o]; shss[tid] += shss[tid + o]; }
                __syncthreads();
            }
            if (tid == 0) {
                float S = shs[0], SS = shss[0];
                float mean = S / (float)NTOT;
                float var = (SS - S * mean) / (float)(NTOT - 1);
                g_stats[0] = mean;
                g_stats[1] = rsqrtf(var);
                g_ctr = 0;   // reset for next graph replay
            }
        }
    } else {
        // ---- w1 transpose + colsum path ----
        const int bid = blockIdx.x - NSTATBLK;
        const int n0 = (bid & 15) * 64;          // HID/64 = 16
        const int k0 = (bid >> 4) * 64;          // SIZE_D/64 = 32
        float (*t)[65] = (float (*)[65])smembuf;

        const int lr = tid >> 4;
        const int lc = (tid & 15) * 4;
#pragma unroll
        for (int i = 0; i < 64; i += 16) {
            float4 v = *(const float4*)(w1 + (size_t)(k0 + lr + i) * HID + n0 + lc);
            t[lr + i][lc + 0] = v.x;
            t[lr + i][lc + 1] = v.y;
            t[lr + i][lc + 2] = v.z;
            t[lr + i][lc + 3] = v.w;
        }
        __syncthreads();

        if (tid < 64) {
            float s = 0.f;
#pragma unroll
            for (int r = 0; r < 64; r++) s += t[r][tid];
            atomicAdd(&g_colsum[n0 + tid], s);
        }

        const int wid = tid >> 5;
        const int lane = tid & 31;
#pragma unroll
        for (int i = 0; i < 64; i += 8) {
            const int r = wid + i;
            const int k = lane * 2;
            __half2 hp = {__float2half_rn(t[k][r]), __float2half_rn(t[k + 1][r])};
            *(__half2*)(w1t + (size_t)(n0 + r) * SIZE_D + k0 + k) = hp;
        }
    }
}

// ---------------- transpose -> fp16, 64x64 tiles (w2) ----------------
__global__ __launch_bounds__(256)
void transpose_half(const float* __restrict__ src,
                    __half* __restrict__ dst, int K, int N) {
    __shared__ float t[64][65];
    const int n0 = blockIdx.x * 64;
    const int k0 = blockIdx.y * 64;
    const int tid = threadIdx.x;

    const int lr = tid >> 4;
    const int lc = (tid & 15) * 4;
#pragma unroll
    for (int i = 0; i < 64; i += 16) {
        float4 v = *(const float4*)(src + (size_t)(k0 + lr + i) * N + n0 + lc);
        t[lr + i][lc + 0] = v.x;
        t[lr + i][lc + 1] = v.y;
        t[lr + i][lc + 2] = v.z;
        t[lr + i][lc + 3] = v.w;
    }
    __syncthreads();

    const int wid = tid >> 5;
    const int lane = tid & 31;
#pragma unroll
    for (int i = 0; i < 64; i += 8) {
        const int r = wid + i;
        const int k = lane * 2;
        __half2 hp = {__float2half_rn(t[k][r]), __float2half_rn(t[k + 1][r])};
        *(__half2*)(dst + (size_t)(n0 + r) * K + k0 + k) = hp;
    }
}

// ---------------- plain fp16 GEMM, NG n-groups per warp ----------------
template <int EPI, int NG>
__global__ __launch_bounds__(256, 2)
void gemm_fp16(const __half* __restrict__ A,
               const __half* __restrict__ B,
               const float* __restrict__ bias,
               const float* __restrict__ colsum,
               __half* __restrict__ C,
               int K, int Nout, int KTILES) {
    constexpr int TILE_B_BYTES = NG * 2048;
    constexpr int STAGE_B = TILE_A_BYTES + TILE_B_BYTES;
    constexpr int GBN = NG * 32;

    extern __shared__ __align__(128) char smem[];
    const uint32_t sb = smem_u32(smem);
    const int tid = threadIdx.x;
    const int wid = tid >> 5;
    const int lane = tid & 31;
    const int wm = wid & 3;
    const int wn = wid >> 2;
    const int m0 = blockIdx.x * GBM;
    const int n0 = blockIdx.y * GBN;

    const int r0c = tid >> 2, c0c = tid & 3;
    const int r1c = (tid + 256) >> 2;

    float acc[2][2 * NG][4];
#pragma unroll
    for (int a = 0; a < 2; a++)
#pragma unroll
        for (int b = 0; b < 2 * NG; b++)
#pragma unroll
            for (int c = 0; c < 4; c++) acc[a][b][c] = 0.f;

    auto load_stage = [&](int s, int kt) {
        const uint32_t base = sb + s * STAGE_B;
        const size_t kof = (size_t)kt * GBK;
        {
            uint32_t so = sw_off(r0c, c0c);
            cp_async16(base + so, A + (size_t)(m0 + r0c) * K + kof + c0c * 8);
            cp_async16(base + TILE_A_BYTES + so,
                       B + (size_t)(n0 + r0c) * K + kof + c0c * 8);
        }
        {
            uint32_t so = sw_off(r1c, c0c);
            cp_async16(base + so, A + (size_t)(m0 + r1c) * K + kof + c0c * 8);
            if (NG == 4)
                cp_async16(base + TILE_A_BYTES + so,
                           B + (size_t)(n0 + r1c) * K + kof + c0c * 8);
        }
    };

#pragma unroll
    for (int s = 0; s < GSTAGES - 1; s++) {
        load_stage(s, s);
        cp_commit();
    }

    const int lrow = lane & 15;
    const int lhalf = lane >> 4;

    int cs = 0;
    int ls = GSTAGES - 1;
    for (int kt = 0; kt < KTILES; kt++) {
        cp_wait<GSTAGES - 2>();
        __syncthreads();

        const int nk = kt + GSTAGES - 1;
        if (nk < KTILES) load_stage(ls, nk);
        cp_commit();

        const uint32_t sA = sb + cs * STAGE_B;
        const uint32_t sB = sA + TILE_A_BYTES;

#pragma unroll
        for (int k16 = 0; k16 < 2; k16++) {
            const int kc = k16 * 2 + lhalf;
            uint32_t afr[2][4];
#pragma unroll
            for (int mt = 0; mt < 2; mt++) {
                int row = wm * 32 + mt * 16 + lrow;
                ldmatrix_x4(afr[mt], sA + sw_off(row, kc));
            }
#pragma unroll
            for (int g = 0; g < NG; g++) {
                int row = wn * (NG * 16) + g * 16 + lrow;
                uint32_t bfr[4];
                ldmatrix_x4(bfr, sB + sw_off(row, kc));
#pragma unroll
                for (int mt = 0; mt < 2; mt++) {
#pragma unroll
                    for (int p = 0; p < 2; p++) {
                        mma16816(acc[mt][g * 2 + p], afr[mt], bfr[p], bfr[2 + p]);
                    }
                }
            }
        }
        cs = (cs + 1 == GSTAGES) ? 0 : cs + 1;
        ls = (ls + 1 == GSTAGES) ? 0 : ls + 1;
    }

    // ---------------- epilogue ----------------
    float mean = 0.f, invstd = 1.f;
    if (EPI == 0) { mean = g_stats[0]; invstd = g_stats[1]; }

    const int r_base = m0 + wm * 32 + (lane >> 2);
    const int c_base = n0 + wn * (NG * 16) + (lane & 3) * 2;

#pragma unroll
    for (int mt = 0; mt < 2; mt++) {
#pragma unroll
        for (int nf = 0; nf < 2 * NG; nf++) {
            const int col = c_base + nf * 8;
            float be0, be1;
            if (EPI == 0) {
                be0 = bias[col]     - mean * invstd * colsum[col];
                be1 = bias[col + 1] - mean * invstd * colsum[col + 1];
            } else {
                be0 = bias[col];
                be1 = bias[col + 1];
            }
#pragma unroll
            for (int hh = 0; hh < 2; hh++) {
                const int row = r_base + mt * 16 + hh * 8;
                float v0 = acc[mt][nf][hh * 2 + 0];
                float v1 = acc[mt][nf][hh * 2 + 1];
                if (EPI == 0) {
                    v0 = fast_tanh(fmaf(invstd, v0, be0));
                    v1 = fast_tanh(fmaf(invstd, v1, be1));
                } else {
                    v0 = fast_tanh(v0 + be0);
                    v1 = fast_tanh(v1 + be1);
                }
                __half2 hp = {__float2half_rn(v0), __float2half_rn(v1)};
                *(__half2*)(C + (size_t)row * Nout + col) = hp;
            }
        }
    }
}

// ---------------- spline (per-row block, 8 chunks) + colsum reset ----------
__global__ __launch_bounds__(256)
void spline_kernel(const __half* __restrict__ net, const float* __restrict__ x_in,
                   const float* __restrict__ logd, float* __restrict__ phi_out,
                   float* __restrict__ log_out) {
    const int b = blockIdx.x;
    const int tid = threadIdx.x;
    const __half* row = net + (size_t)b * OUTW;

    __shared__ float sh[256 * NC];
    __shared__ float red[256];

    // reset colsum for the next graph replay (w1/stats already consumed it)
    if (b < 4) g_colsum[b * 256 + tid] = 0.f;

    float lsum = 0.f;

    for (int chunk = 0; chunk < 8; chunk++) {
        __syncthreads();
        const __half2* rowc = (const __half2*)(row + (size_t)chunk * 256 * NC);
        for (int i = tid; i < 128 * NC; i += 256) {
            float2 v = __half22float2(rowc[i]);
            sh[2 * i]     = v.x;
            sh[2 * i + 1] = v.y;
        }
        __syncthreads();

        const int s = chunk * 256 + tid;
        const float* p = sh + tid * NC;

        float hr[9], wr[8];
#pragma unroll
        for (int c = 0; c < 9; c++) hr[c] = p[c];
#pragma unroll
        for (int c = 0; c < 8; c++) wr[c] = p[9 + c];

        float m = wr[0];
#pragma unroll
        for (int c = 1; c < 8; c++) m = fmaxf(m, wr[c]);
        float wn[8];
        float wsum = 0.f;
#pragma unroll
        for (int c = 0; c < 8; c++) { wn[c] = __expf(wr[c] - m); wsum += wn[c]; }
        float winv = 1.0f / wsum;
#pragma unroll
        for (int c = 0; c < 8; c++) wn[c] *= winv;

        float eh[9];
#pragma unroll
        for (int c = 0; c < 9; c++) eh[c] = __expf(hr[c]);
        float denom = 0.f;
#pragma unroll
        for (int c = 0; c < 8; c++) denom += 0.5f * wn[c] * (eh[c] + eh[c + 1]);
        float dinv = 1.0f / denom;
        float hn[9];
#pragma unroll
        for (int c = 0; c < 9; c++) hn[c] = eh[c] * dinv;

        const float x = x_in[(size_t)b * SIZE_D + s] * 0.31830988618379067154f;

        float cum = 0.f, phicum = 0.f;
        float wk = wn[0], hk = hn[0], hk1 = hn[1];
        float xkm1 = -EPS_C, phikm1 = 0.f;
#pragma unroll
        for (int i = 0; i < 7; i++) {
            float trap = 0.5f * wn[i] * (hn[i] + hn[i + 1]);
            cum += wn[i];
            phicum += trap;
            bool c = (cum < x);
            wk     = c ? wn[i + 1] : wk;
            hk     = c ? hn[i + 1] : hk;
            hk1    = c ? hn[i + 2] : hk1;
            xkm1   = c ? cum      : xkm1;
            phikm1 = c ? phicum   : phikm1;
        }

        float alpha = (x - xkm1) / wk;
        float phi = phikm1 + alpha * hk * wk
                  + 0.5f * alpha * alpha * (hk1 - hk) * wk;
        phi_out[(size_t)b * SIZE_D + s] = phi;
        lsum += __logf(hk + alpha * (hk1 - hk));
    }

    red[tid] = lsum;
    __syncthreads();
    for (int o = 128; o > 0; o >>= 1) {
        if (tid < o) red[tid] += red[tid + o];
        __syncthreads();
    }
    if (tid == 0) log_out[b] = logd[b] - red[0];
}

// ---------------- launch ----------------
extern "C" void kernel_launch(void* const* d_in, const int* in_sizes, int n_in,
                              void* d_out, int out_size) {
    (void)in_sizes; (void)n_in; (void)out_size;
    const float* x_in      = (const float*)d_in[0];
    const float* x_passive = (const float*)d_in[1];
    const float* log_dens  = (const float*)d_in[2];
    const float* w1        = (const float*)d_in[3];
    const float* b1        = (const float*)d_in[4];
    const float* w2        = (const float*)d_in[5];
    const float* b2        = (const float*)d_in[6];

    float* out_phi = (float*)d_out;
    float* out_log = (float*)d_out + (size_t)NTOT;

    __half *xh, *w1t, *hbuf, *w2t, *nbuf;
    float *csum;
    cudaGetSymbolAddress((void**)&xh, g_xh);
    cudaGetSymbolAddress((void**)&w1t, g_w1t);
    cudaGetSymbolAddress((void**)&hbuf, g_h);
    cudaGetSymbolAddress((void**)&w2t, g_w2t);
    cudaGetSymbolAddress((void**)&nbuf, g_net);
    cudaGetSymbolAddress((void**)&csum, g_colsum);

    const int SMEM4 = GSTAGES * (TILE_A_BYTES + 4 * 2048);  // 81920
    cudaFuncSetAttribute((const void*)gemm_fp16<0, 4>,
                         cudaFuncAttributeMaxDynamicSharedMemorySize, SMEM4);
    cudaFuncSetAttribute((const void*)gemm_fp16<1, 4>,
                         cudaFuncAttributeMaxDynamicSharedMemorySize, SMEM4);

    // 1) fused prep: stats(+finalize) + x fp16 + w1 transpose/colsum
    prep_fused<<<NSTATBLK + NW1TBLK, 256>>>(x_passive, xh, w1, w1t);
    // 2) w2 transpose
    transpose_half<<<dim3(OUTW / 64, HID / 64), 256>>>(w2, w2t, HID, OUTW);
    // 3) GEMM1: h = tanh(xs @ w1 + b1) -> fp16  (128x128)
    gemm_fp16<0, 4><<<dim3(BATCH / GBM, HID / 128), 256, SMEM4>>>(
        xh, w1t, b1, csum, hbuf, SIZE_D, HID, SIZE_D / GBK);
    // 4) GEMM2: net = tanh(h @ w2 + b2) -> fp16 (128x128)  [ncu capture slot]
    gemm_fp16<1, 4><<<dim3(BATCH / GBM, OUTW / 128), 256, SMEM4>>>(
        hbuf, w2t, b2, nullptr, nbuf, HID, OUTW, HID / GBK);
    // 5) spline + per-row log reduction + colsum reset for next replay
    spline_kernel<<<BATCH, 256>>>(nbuf, x_in, log_dens, out_phi, out_log);
}

// round 13
// speedup vs baseline: 1.1499x; 1.0818x over previous
#include <cuda_runtime.h>
#include <cuda_fp16.h>
#include <math.h>
#include <stdint.h>

// ---------------- problem constants ----------------
#define BATCH 2048
#define SIZE_D 2048
#define HID 1024
#define NC 17
#define OUTW (SIZE_D * NC)   // 34816
#define NTOT (BATCH * SIZE_D)
#define EPS_C 1e-6f
#define NSTATBLK (NTOT / 4 / 256)   // 4096
#define NW1TBLK ((HID / 64) * (SIZE_D / 64))   // 512

// ---------------- GEMM tiling ----------------
#define GBM 128
#define GBK 32
#define GSTAGES 4
#define TILE_A_BYTES 8192   // 128 rows x 64B

// ---------------- device scratch ----------------
__device__ __half g_xh[(size_t)NTOT];
__device__ __half g_w1t[(size_t)HID * SIZE_D];
__device__ __half g_h[(size_t)BATCH * HID];
__device__ __half g_w2t[(size_t)OUTW * HID];
__device__ __half g_net[(size_t)BATCH * OUTW];
__device__ float g_colsum[HID];          // zero at load; re-zeroed by spline
__device__ float g_part_s[NSTATBLK];
__device__ float g_part_ss[NSTATBLK];
__device__ float g_stats[2];
__device__ unsigned int g_ctr;

// ---------------- PTX helpers ----------------
__device__ __forceinline__ uint32_t smem_u32(const void* p) {
    uint32_t a;
    asm("{ .reg .u64 t; cvta.to.shared.u64 t, %1; cvt.u32.u64 %0, t; }"
        : "=r"(a) : "l"(p));
    return a;
}
__device__ __forceinline__ void cp_async16(uint32_t sa, const void* ga) {
    asm volatile("cp.async.cg.shared.global [%0], [%1], 16;"
                 :: "r"(sa), "l"(ga) : "memory");
}
__device__ __forceinline__ void cp_commit() {
    asm volatile("cp.async.commit_group;" ::: "memory");
}
template <int N>
__device__ __forceinline__ void cp_wait() {
    asm volatile("cp.async.wait_group %0;" :: "n"(N) : "memory");
}
__device__ __forceinline__ void ldmatrix_x4(uint32_t* r, uint32_t addr) {
    asm volatile("ldmatrix.sync.aligned.m8n8.x4.shared.b16 {%0,%1,%2,%3}, [%4];"
                 : "=r"(r[0]), "=r"(r[1]), "=r"(r[2]), "=r"(r[3])
                 : "r"(addr));
}
__device__ __forceinline__ void mma16816(float* c, const uint32_t* a,
                                         uint32_t b0, uint32_t b1) {
    asm volatile(
        "mma.sync.aligned.m16n8k16.row.col.f32.f16.f16.f32 "
        "{%0,%1,%2,%3}, {%4,%5,%6,%7}, {%8,%9}, {%0,%1,%2,%3};"
        : "+f"(c[0]), "+f"(c[1]), "+f"(c[2]), "+f"(c[3])
        : "r"(a[0]), "r"(a[1]), "r"(a[2]), "r"(a[3]), "r"(b0), "r"(b1));
}
__device__ __forceinline__ uint32_t sw_off(int row, int ch) {
    return ((uint32_t)row << 6) + (((ch ^ (row >> 1)) & 3) << 4);
}
__device__ __forceinline__ float fast_tanh(float x) {
    float e = __expf(2.0f * x);
    return 1.0f - 2.0f / (e + 1.0f);
}

// ---------------- fused prep: stats(+finalize) and w1 transpose+colsum ------
__global__ __launch_bounds__(256)
void prep_fused(const float* __restrict__ xp, __half* __restrict__ xh,
                const float* __restrict__ w1, __half* __restrict__ w1t) {
    __shared__ float smembuf[64 * 65];
    __shared__ int slast;
    const int tid = threadIdx.x;

    if (blockIdx.x < NSTATBLK) {
        const int i = blockIdx.x * 256 + tid;
        float4 v = ((const float4*)xp)[i];

        __half2 p0 = {__float2half_rn(v.x), __float2half_rn(v.y)};
        __half2 p1 = {__float2half_rn(v.z), __float2half_rn(v.w)};
        uint2 hv = {*(uint32_t*)&p0, *(uint32_t*)&p1};
        ((uint2*)xh)[i] = hv;

        float* shs = smembuf;
        float* shss = smembuf + 256;
        float s = v.x + v.y + v.z + v.w;
        float ss = v.x * v.x + v.y * v.y + v.z * v.z + v.w * v.w;
        shs[tid] = s; shss[tid] = ss;
        __syncthreads();
        for (int o = 128; o > 0; o >>= 1) {
            if (tid < o) { shs[tid] += shs[tid + o]; shss[tid] += shss[tid + o]; }
            __syncthreads();
        }
        if (tid == 0) {
            g_part_s[blockIdx.x] = shs[0];
            g_part_ss[blockIdx.x] = shss[0];
            __threadfence();
            unsigned int old = atomicAdd(&g_ctr, 1u);
            slast = (old == NSTATBLK - 1) ? 1 : 0;
        }
        __syncthreads();
        if (slast) {
            __threadfence();
            float fs = 0.f, fss = 0.f;
            for (int k = tid; k < NSTATBLK; k += 256) {
                fs += g_part_s[k]; fss += g_part_ss[k];
            }
            shs[tid] = fs; shss[tid] = fss;
            __syncthreads();
            for (int o = 128; o > 0; o >>= 1) {
                if (tid < o) { shs[tid] += shs[tid + o]; shss[tid] += shss[tid + o]; }
                __syncthreads();
            }
            if (tid == 0) {
                float S = shs[0], SS = shss[0];
                float mean = S / (float)NTOT;
                float var = (SS - S * mean) / (float)(NTOT - 1);
                g_stats[0] = mean;
                g_stats[1] = rsqrtf(var);
                g_ctr = 0;
            }
        }
    } else {
        const int bid = blockIdx.x - NSTATBLK;
        const int n0 = (bid & 15) * 64;
        const int k0 = (bid >> 4) * 64;
        float (*t)[65] = (float (*)[65])smembuf;

        const int lr = tid >> 4;
        const int lc = (tid & 15) * 4;
#pragma unroll
        for (int i = 0; i < 64; i += 16) {
            float4 v = *(const float4*)(w1 + (size_t)(k0 + lr + i) * HID + n0 + lc);
            t[lr + i][lc + 0] = v.x;
            t[lr + i][lc + 1] = v.y;
            t[lr + i][lc + 2] = v.z;
            t[lr + i][lc + 3] = v.w;
        }
        __syncthreads();

        if (tid < 64) {
            float s = 0.f;
#pragma unroll
            for (int r = 0; r < 64; r++) s += t[r][tid];
            atomicAdd(&g_colsum[n0 + tid], s);
        }

        const int wid = tid >> 5;
        const int lane = tid & 31;
#pragma unroll
        for (int i = 0; i < 64; i += 8) {
            const int r = wid + i;
            const int k = lane * 2;
            __half2 hp = {__float2half_rn(t[k][r]), __float2half_rn(t[k + 1][r])};
            *(__half2*)(w1t + (size_t)(n0 + r) * SIZE_D + k0 + k) = hp;
        }
    }
}

// ---------------- transpose -> fp16, 64x64 tiles (w2) ----------------
__global__ __launch_bounds__(256)
void transpose_half(const float* __restrict__ src,
                    __half* __restrict__ dst, int K, int N) {
    __shared__ float t[64][65];
    const int n0 = blockIdx.x * 64;
    const int k0 = blockIdx.y * 64;
    const int tid = threadIdx.x;

    const int lr = tid >> 4;
    const int lc = (tid & 15) * 4;
#pragma unroll
    for (int i = 0; i < 64; i += 16) {
        float4 v = *(const float4*)(src + (size_t)(k0 + lr + i) * N + n0 + lc);
        t[lr + i][lc + 0] = v.x;
        t[lr + i][lc + 1] = v.y;
        t[lr + i][lc + 2] = v.z;
        t[lr + i][lc + 3] = v.w;
    }
    __syncthreads();

    const int wid = tid >> 5;
    const int lane = tid & 31;
#pragma unroll
    for (int i = 0; i < 64; i += 8) {
        const int r = wid + i;
        const int k = lane * 2;
        __half2 hp = {__float2half_rn(t[k][r]), __float2half_rn(t[k + 1][r])};
        *(__half2*)(dst + (size_t)(n0 + r) * K + k0 + k) = hp;
    }
}

// ---------------- plain fp16 GEMM, strength-reduced mainloop ----------------
// Pointer-increment global addressing, precomputed ldmatrix offsets,
// stage-unrolled pipeline (GSTAGES=4 divides KTILES).
template <int EPI, int NG>
__global__ __launch_bounds__(256, 2)
void gemm_fp16(const __half* __restrict__ A,
               const __half* __restrict__ B,
               const float* __restrict__ bias,
               const float* __restrict__ colsum,
               __half* __restrict__ C,
               int K, int Nout, int KTILES) {
    constexpr int TILE_B_BYTES = NG * 2048;
    constexpr int STAGE_B = TILE_A_BYTES + TILE_B_BYTES;

    extern __shared__ __align__(128) char smem[];
    const uint32_t sb = smem_u32(smem);
    const int tid = threadIdx.x;
    const int wid = tid >> 5;
    const int lane = tid & 31;
    const int wm = wid & 3;
    const int wn = wid >> 2;
    const int m0 = blockIdx.x * GBM;
    const int n0 = blockIdx.y * (NG * 32);

    // cp.async mapping (loop-invariant)
    const int r0c = tid >> 2, c0c = tid & 3;
    const int r1c = (tid + 256) >> 2;
    const uint32_t soA0 = sw_off(r0c, c0c);
    const uint32_t soA1 = sw_off(r1c, c0c);

    const __half* pA0 = A + (size_t)(m0 + r0c) * K + c0c * 8;
    const __half* pA1 = A + (size_t)(m0 + r1c) * K + c0c * 8;
    const __half* pB0 = B + (size_t)(n0 + r0c) * K + c0c * 8;
    const __half* pB1 = B + (size_t)(n0 + (NG == 4 ? r1c : r0c)) * K + c0c * 8;

    auto load_stage_at = [&](uint32_t base) {
        cp_async16(base + soA0, pA0);
        cp_async16(base + TILE_A_BYTES + soA0, pB0);
        cp_async16(base + soA1, pA1);
        if (NG == 4) cp_async16(base + TILE_A_BYTES + soA1, pB1);
        pA0 += GBK; pA1 += GBK; pB0 += GBK;
        if (NG == 4) pB1 += GBK;
    };

    // precomputed ldmatrix smem offsets (loop-invariant)
    const int lrow = lane & 15;
    const int lhalf = lane >> 4;
    uint32_t offA[2][2], offB[2][NG];
#pragma unroll
    for (int k16 = 0; k16 < 2; k16++) {
        const int kc = k16 * 2 + lhalf;
#pragma unroll
        for (int mt = 0; mt < 2; mt++)
            offA[k16][mt] = sw_off(wm * 32 + mt * 16 + lrow, kc);
#pragma unroll
        for (int g = 0; g < NG; g++)
            offB[k16][g] = TILE_A_BYTES + sw_off(wn * (NG * 16) + g * 16 + lrow, kc);
    }

    float acc[2][2 * NG][4];
#pragma unroll
    for (int a = 0; a < 2; a++)
#pragma unroll
        for (int b = 0; b < 2 * NG; b++)
#pragma unroll
            for (int c = 0; c < 4; c++) acc[a][b][c] = 0.f;

    // prologue: fill GSTAGES-1 stages
#pragma unroll
    for (int s = 0; s < GSTAGES - 1; s++) {
        load_stage_at(sb + s * STAGE_B);
        cp_commit();
    }

    // mainloop: stage-unrolled; stage indices are compile-time constants
    for (int kt = 0; kt < KTILES; kt += GSTAGES) {
#pragma unroll
        for (int s = 0; s < GSTAGES; s++) {
            cp_wait<GSTAGES - 2>();
            __syncthreads();

            if (kt + s + GSTAGES - 1 < KTILES)
                load_stage_at(sb + ((s + GSTAGES - 1) % GSTAGES) * STAGE_B);
            cp_commit();

            const uint32_t st = sb + s * STAGE_B;
#pragma unroll
            for (int k16 = 0; k16 < 2; k16++) {
                uint32_t afr[2][4];
#pragma unroll
                for (int mt = 0; mt < 2; mt++)
                    ldmatrix_x4(afr[mt], st + offA[k16][mt]);
#pragma unroll
                for (int g = 0; g < NG; g++) {
                    uint32_t bfr[4];
                    ldmatrix_x4(bfr, st + offB[k16][g]);
#pragma unroll
                    for (int mt = 0; mt < 2; mt++) {
#pragma unroll
                        for (int p = 0; p < 2; p++) {
                            mma16816(acc[mt][g * 2 + p], afr[mt],
                                     bfr[p], bfr[2 + p]);
                        }
                    }
                }
            }
        }
    }

    // ---------------- epilogue ----------------
    float mean = 0.f, invstd = 1.f;
    if (EPI == 0) { mean = g_stats[0]; invstd = g_stats[1]; }

    const int r_base = m0 + wm * 32 + (lane >> 2);
    const int c_base = n0 + wn * (NG * 16) + (lane & 3) * 2;

#pragma unroll
    for (int mt = 0; mt < 2; mt++) {
#pragma unroll
        for (int nf = 0; nf < 2 * NG; nf++) {
            const int col = c_base + nf * 8;
            float be0, be1;
            if (EPI == 0) {
                be0 = bias[col]     - mean * invstd * colsum[col];
                be1 = bias[col + 1] - mean * invstd * colsum[col + 1];
            } else {
                be0 = bias[col];
                be1 = bias[col + 1];
            }
#pragma unroll
            for (int hh = 0; hh < 2; hh++) {
                const int row = r_base + mt * 16 + hh * 8;
                float v0 = acc[mt][nf][hh * 2 + 0];
                float v1 = acc[mt][nf][hh * 2 + 1];
                if (EPI == 0) {
                    v0 = fast_tanh(fmaf(invstd, v0, be0));
                    v1 = fast_tanh(fmaf(invstd, v1, be1));
                } else {
                    v0 = fast_tanh(v0 + be0);
                    v1 = fast_tanh(v1 + be1);
                }
                __half2 hp = {__float2half_rn(v0), __float2half_rn(v1)};
                *(__half2*)(C + (size_t)row * Nout + col) = hp;
            }
        }
    }
}

// ---------------- spline (per-row block, 8 chunks) + colsum reset ----------
__global__ __launch_bounds__(256)
void spline_kernel(const __half* __restrict__ net, const float* __restrict__ x_in,
                   const float* __restrict__ logd, float* __restrict__ phi_out,
                   float* __restrict__ log_out) {
    const int b = blockIdx.x;
    const int tid = threadIdx.x;
    const __half* row = net + (size_t)b * OUTW;

    __shared__ float sh[256 * NC];
    __shared__ float red[256];

    if (b < 4) g_colsum[b * 256 + tid] = 0.f;

    float lsum = 0.f;

    for (int chunk = 0; chunk < 8; chunk++) {
        __syncthreads();
        const __half2* rowc = (const __half2*)(row + (size_t)chunk * 256 * NC);
        for (int i = tid; i < 128 * NC; i += 256) {
            float2 v = __half22float2(rowc[i]);
            sh[2 * i]     = v.x;
            sh[2 * i + 1] = v.y;
        }
        __syncthreads();

        const int s = chunk * 256 + tid;
        const float* p = sh + tid * NC;

        float hr[9], wr[8];
#pragma unroll
        for (int c = 0; c < 9; c++) hr[c] = p[c];
#pragma unroll
        for (int c = 0; c < 8; c++) wr[c] = p[9 + c];

        float m = wr[0];
#pragma unroll
        for (int c = 1; c < 8; c++) m = fmaxf(m, wr[c]);
        float wn[8];
        float wsum = 0.f;
#pragma unroll
        for (int c = 0; c < 8; c++) { wn[c] = __expf(wr[c] - m); wsum += wn[c]; }
        float winv = 1.0f / wsum;
#pragma unroll
        for (int c = 0; c < 8; c++) wn[c] *= winv;

        float eh[9];
#pragma unroll
        for (int c = 0; c < 9; c++) eh[c] = __expf(hr[c]);
        float denom = 0.f;
#pragma unroll
        for (int c = 0; c < 8; c++) denom += 0.5f * wn[c] * (eh[c] + eh[c + 1]);
        float dinv = 1.0f / denom;
        float hn[9];
#pragma unroll
        for (int c = 0; c < 9; c++) hn[c] = eh[c] * dinv;

        const float x = x_in[(size_t)b * SIZE_D + s] * 0.31830988618379067154f;

        float cum = 0.f, phicum = 0.f;
        float wk = wn[0], hk = hn[0], hk1 = hn[1];
        float xkm1 = -EPS_C, phikm1 = 0.f;
#pragma unroll
        for (int i = 0; i < 7; i++) {
            float trap = 0.5f * wn[i] * (hn[i] + hn[i + 1]);
            cum += wn[i];
            phicum += trap;
            bool c = (cum < x);
            wk     = c ? wn[i + 1] : wk;
            hk     = c ? hn[i + 1] : hk;
            hk1    = c ? hn[i + 2] : hk1;
            xkm1   = c ? cum      : xkm1;
            phikm1 = c ? phicum   : phikm1;
        }

        float alpha = (x - xkm1) / wk;
        float phi = phikm1 + alpha * hk * wk
                  + 0.5f * alpha * alpha * (hk1 - hk) * wk;
        phi_out[(size_t)b * SIZE_D + s] = phi;
        lsum += __logf(hk + alpha * (hk1 - hk));
    }

    red[tid] = lsum;
    __syncthreads();
    for (int o = 128; o > 0; o >>= 1) {
        if (tid < o) red[tid] += red[tid + o];
        __syncthreads();
    }
    if (tid == 0) log_out[b] = logd[b] - red[0];
}

// ---------------- launch ----------------
extern "C" void kernel_launch(void* const* d_in, const int* in_sizes, int n_in,
                              void* d_out, int out_size) {
    (void)in_sizes; (void)n_in; (void)out_size;
    const float* x_in      = (const float*)d_in[0];
    const float* x_passive = (const float*)d_in[1];
    const float* log_dens  = (const float*)d_in[2];
    const float* w1        = (const float*)d_in[3];
    const float* b1        = (const float*)d_in[4];
    const float* w2        = (const float*)d_in[5];
    const float* b2        = (const float*)d_in[6];

    float* out_phi = (float*)d_out;
    float* out_log = (float*)d_out + (size_t)NTOT;

    __half *xh, *w1t, *hbuf, *w2t, *nbuf;
    float *csum;
    cudaGetSymbolAddress((void**)&xh, g_xh);
    cudaGetSymbolAddress((void**)&w1t, g_w1t);
    cudaGetSymbolAddress((void**)&hbuf, g_h);
    cudaGetSymbolAddress((void**)&w2t, g_w2t);
    cudaGetSymbolAddress((void**)&nbuf, g_net);
    cudaGetSymbolAddress((void**)&csum, g_colsum);

    const int SMEM4 = GSTAGES * (TILE_A_BYTES + 4 * 2048);  // 65536
    cudaFuncSetAttribute((const void*)gemm_fp16<0, 4>,
                         cudaFuncAttributeMaxDynamicSharedMemorySize, SMEM4);
    cudaFuncSetAttribute((const void*)gemm_fp16<1, 4>,
                         cudaFuncAttributeMaxDynamicSharedMemorySize, SMEM4);

    // 1) fused prep: stats(+finalize) + x fp16 + w1 transpose/colsum
    prep_fused<<<NSTATBLK + NW1TBLK, 256>>>(x_passive, xh, w1, w1t);
    // 2) w2 transpose
    transpose_half<<<dim3(OUTW / 64, HID / 64), 256>>>(w2, w2t, HID, OUTW);
    // 3) GEMM1: h = tanh(xs @ w1 + b1) -> fp16  (128x128)
    gemm_fp16<0, 4><<<dim3(BATCH / GBM, HID / 128), 256, SMEM4>>>(
        xh, w1t, b1, csum, hbuf, SIZE_D, HID, SIZE_D / GBK);
    // 4) GEMM2: net = tanh(h @ w2 + b2) -> fp16 (128x128)  [ncu capture slot]
    gemm_fp16<1, 4><<<dim3(BATCH / GBM, OUTW / 128), 256, SMEM4>>>(
        hbuf, w2t, b2, nullptr, nbuf, HID, OUTW, HID / GBK);
    // 5) spline + per-row log reduction + colsum reset for next replay
    spline_kernel<<<BATCH, 256>>>(nbuf, x_in, log_dens, out_phi, out_log);
}

// round 14
// speedup vs baseline: 1.1833x; 1.0291x over previous
#include <cuda_runtime.h>
#include <cuda_fp16.h>
#include <math.h>
#include <stdint.h>

// ---------------- problem constants ----------------
#define BATCH 2048
#define SIZE_D 2048
#define HID 1024
#define NC 17
#define OUTW (SIZE_D * NC)   // 34816
#define NTOT (BATCH * SIZE_D)
#define EPS_C 1e-6f
#define NSTATBLK (NTOT / 4 / 256)              // 4096
#define NW1T ((HID / 64) * (SIZE_D / 64))      // 512
#define NW2T ((OUTW / 64) * (HID / 64))        // 8704

// ---------------- GEMM tiling: 128x128 block, GBK=64 ----------------
#define GBM 128
#define GBK 64
#define GSTAGES 3
#define TILE_BYTES 16384                       // 128 rows x 128B
#define STAGE_B (2 * TILE_BYTES)               // 32768
#define GEMM_SMEM (GSTAGES * STAGE_B)          // 98304 -> 2 CTAs/SM

// ---------------- device scratch ----------------
__device__ __half g_xh[(size_t)NTOT];
__device__ __half g_w1t[(size_t)HID * SIZE_D];
__device__ __half g_h[(size_t)BATCH * HID];
__device__ __half g_w2t[(size_t)OUTW * HID];
__device__ __half g_net[(size_t)BATCH * OUTW];
__device__ float g_colsum[HID];          // zero at load; re-zeroed by spline
__device__ float g_part_s[NSTATBLK];
__device__ float g_part_ss[NSTATBLK];
__device__ float g_stats[2];
__device__ unsigned int g_ctr;

// ---------------- PTX helpers ----------------
__device__ __forceinline__ uint32_t smem_u32(const void* p) {
    uint32_t a;
    asm("{ .reg .u64 t; cvta.to.shared.u64 t, %1; cvt.u32.u64 %0, t; }"
        : "=r"(a) : "l"(p));
    return a;
}
__device__ __forceinline__ void cp_async16(uint32_t sa, const void* ga) {
    asm volatile("cp.async.cg.shared.global [%0], [%1], 16;"
                 :: "r"(sa), "l"(ga) : "memory");
}
__device__ __forceinline__ void cp_commit() {
    asm volatile("cp.async.commit_group;" ::: "memory");
}
template <int N>
__device__ __forceinline__ void cp_wait() {
    asm volatile("cp.async.wait_group %0;" :: "n"(N) : "memory");
}
__device__ __forceinline__ void ldmatrix_x4(uint32_t* r, uint32_t addr) {
    asm volatile("ldmatrix.sync.aligned.m8n8.x4.shared.b16 {%0,%1,%2,%3}, [%4];"
                 : "=r"(r[0]), "=r"(r[1]), "=r"(r[2]), "=r"(r[3])
                 : "r"(addr));
}
__device__ __forceinline__ void mma16816(float* c, const uint32_t* a,
                                         uint32_t b0, uint32_t b1) {
    asm volatile(
        "mma.sync.aligned.m16n8k16.row.col.f32.f16.f16.f32 "
        "{%0,%1,%2,%3}, {%4,%5,%6,%7}, {%8,%9}, {%0,%1,%2,%3};"
        : "+f"(c[0]), "+f"(c[1]), "+f"(c[2]), "+f"(c[3])
        : "r"(a[0]), "r"(a[1]), "r"(a[2]), "r"(a[3]), "r"(b0), "r"(b1));
}
// 128B-row swizzle: 16B chunk index XOR (row & 7)
__device__ __forceinline__ uint32_t sw128(int row, int ch) {
    return ((uint32_t)row << 7) + ((uint32_t)((ch ^ (row & 7)) & 7) << 4);
}
__device__ __forceinline__ float fast_tanh(float x) {
    float e = __expf(2.0f * x);
    return 1.0f - 2.0f / (e + 1.0f);
}

// ---------------- fused prep: stats + w1t + w2t ----------------
__device__ __forceinline__ void transpose_tile(
    const float* __restrict__ src, __half* __restrict__ dst,
    float* smembuf, int K, int N, int n0, int k0, int docolsum, int tid) {
    float (*t)[65] = (float (*)[65])smembuf;
    const int lr = tid >> 4;
    const int lc = (tid & 15) * 4;
#pragma unroll
    for (int i = 0; i < 64; i += 16) {
        float4 v = *(const float4*)(src + (size_t)(k0 + lr + i) * N + n0 + lc);
        t[lr + i][lc + 0] = v.x;
        t[lr + i][lc + 1] = v.y;
        t[lr + i][lc + 2] = v.z;
        t[lr + i][lc + 3] = v.w;
    }
    __syncthreads();
    if (docolsum && tid < 64) {
        float s = 0.f;
#pragma unroll
        for (int r = 0; r < 64; r++) s += t[r][tid];
        atomicAdd(&g_colsum[n0 + tid], s);
    }
    const int wid = tid >> 5;
    const int lane = tid & 31;
#pragma unroll
    for (int i = 0; i < 64; i += 8) {
        const int r = wid + i;
        const int k = lane * 2;
        __half2 hp = {__float2half_rn(t[k][r]), __float2half_rn(t[k + 1][r])};
        *(__half2*)(dst + (size_t)(n0 + r) * K + k0 + k) = hp;
    }
}

__global__ __launch_bounds__(256)
void prep_fused(const float* __restrict__ xp, __half* __restrict__ xh,
                const float* __restrict__ w1, __half* __restrict__ w1t,
                const float* __restrict__ w2, __half* __restrict__ w2t) {
    __shared__ float smembuf[64 * 65];
    __shared__ int slast;
    const int tid = threadIdx.x;

    if (blockIdx.x < NSTATBLK) {
        const int i = blockIdx.x * 256 + tid;
        float4 v = ((const float4*)xp)[i];

        __half2 p0 = {__float2half_rn(v.x), __float2half_rn(v.y)};
        __half2 p1 = {__float2half_rn(v.z), __float2half_rn(v.w)};
        uint2 hv = {*(uint32_t*)&p0, *(uint32_t*)&p1};
        ((uint2*)xh)[i] = hv;

        float* shs = smembuf;
        float* shss = smembuf + 256;
        float s = v.x + v.y + v.z + v.w;
        float ss = v.x * v.x + v.y * v.y + v.z * v.z + v.w * v.w;
        shs[tid] = s; shss[tid] = ss;
        __syncthreads();
        for (int o = 128; o > 0; o >>= 1) {
            if (tid < o) { shs[tid] += shs[tid + o]; shss[tid] += shss[tid + o]; }
            __syncthreads();
        }
        if (tid == 0) {
            g_part_s[blockIdx.x] = shs[0];
            g_part_ss[blockIdx.x] = shss[0];
            __threadfence();
            unsigned int old = atomicAdd(&g_ctr, 1u);
            slast = (old == NSTATBLK - 1) ? 1 : 0;
        }
        __syncthreads();
        if (slast) {
            __threadfence();
            float fs = 0.f, fss = 0.f;
            for (int k = tid; k < NSTATBLK; k += 256) {
                fs += g_part_s[k]; fss += g_part_ss[k];
            }
            shs[tid] = fs; shss[tid] = fss;
            __syncthreads();
            for (int o = 128; o > 0; o >>= 1) {
                if (tid < o) { shs[tid] += shs[tid + o]; shss[tid] += shss[tid + o]; }
                __syncthreads();
            }
            if (tid == 0) {
                float S = shs[0], SS = shss[0];
                float mean = S / (float)NTOT;
                float var = (SS - S * mean) / (float)(NTOT - 1);
                g_stats[0] = mean;
                g_stats[1] = rsqrtf(var);
                g_ctr = 0;
            }
        }
    } else if (blockIdx.x < NSTATBLK + NW1T) {
        const int bid = blockIdx.x - NSTATBLK;
        const int n0 = (bid & 15) * 64;          // HID/64 = 16
        const int k0 = (bid >> 4) * 64;
        transpose_tile(w1, w1t, smembuf, SIZE_D, HID, n0, k0, 1, tid);
    } else {
        const int bid = blockIdx.x - NSTATBLK - NW1T;
        const int n0 = (bid % (OUTW / 64)) * 64;
        const int k0 = (bid / (OUTW / 64)) * 64;
        transpose_tile(w2, w2t, smembuf, HID, OUTW, n0, k0, 0, tid);
    }
}

// ---------------- fp16 GEMM: 128x128 tile, GBK=64, delta-swizzled offsets ---
template <int EPI>
__global__ __launch_bounds__(256, 2)
void gemm_fp16(const __half* __restrict__ A,
               const __half* __restrict__ B,
               const float* __restrict__ bias,
               const float* __restrict__ colsum,
               __half* __restrict__ C,
               int K, int Nout, int KTILES) {
    extern __shared__ __align__(128) char smem[];
    const uint32_t sb = smem_u32(smem);
    const int tid = threadIdx.x;
    const int wid = tid >> 5;
    const int lane = tid & 31;
    const int wm = wid & 3;       // M warp 0..3 (32 rows each)
    const int wn = wid >> 2;      // N warp 0..1 (64 cols each)
    const int m0 = blockIdx.x * GBM;
    const int n0 = blockIdx.y * 128;

    // cp.async mapping: thread covers rows r, r+32, r+64, r+96 at chunk c
    const int rr = tid >> 3;          // 0..31
    const int cc = tid & 7;           // chunk 0..7
    const uint32_t so = sw128(rr, cc);   // same swizzle at +32/64/96 rows

    const __half* pA = A + (size_t)(m0 + rr) * K + cc * 8;
    const __half* pB = B + (size_t)(n0 + rr) * K + cc * 8;
    const size_t k32 = (size_t)32 * K;
    const size_t k64 = (size_t)64 * K;
    const size_t k96 = (size_t)96 * K;

    auto load_stage_at = [&](uint32_t base) {
        cp_async16(base + so,          pA);
        cp_async16(base + so + 4096,   pA + k32);
        cp_async16(base + so + 8192,   pA + k64);
        cp_async16(base + so + 12288,  pA + k96);
        const uint32_t bb = base + TILE_BYTES;
        cp_async16(bb + so,            pB);
        cp_async16(bb + so + 4096,     pB + k32);
        cp_async16(bb + so + 8192,     pB + k64);
        cp_async16(bb + so + 12288,    pB + k96);
        pA += GBK; pB += GBK;
    };

    // ldmatrix offsets: rows differing by 16 share (row&7) -> +2048 delta
    const int lrow = lane & 15;
    const int lhalf = lane >> 4;
    uint32_t offA[4], offB[4];
#pragma unroll
    for (int k16 = 0; k16 < 4; k16++) {
        const int kc = k16 * 2 + lhalf;
        offA[k16] = sw128(wm * 32 + lrow, kc);
        offB[k16] = TILE_BYTES + sw128(wn * 64 + lrow, kc);
    }

    float acc[2][8][4];
#pragma unroll
    for (int a = 0; a < 2; a++)
#pragma unroll
        for (int b = 0; b < 8; b++)
#pragma unroll
            for (int c = 0; c < 4; c++) acc[a][b][c] = 0.f;

    // prologue
#pragma unroll
    for (int s = 0; s < GSTAGES - 1; s++) {
        load_stage_at(sb + s * STAGE_B);
        cp_commit();
    }

    int cs = 0;
    int ls = GSTAGES - 1;
    for (int kt = 0; kt < KTILES; kt++) {
        cp_wait<GSTAGES - 2>();
        __syncthreads();

        if (kt + GSTAGES - 1 < KTILES) load_stage_at(sb + ls * STAGE_B);
        cp_commit();

        const uint32_t st = sb + cs * STAGE_B;
#pragma unroll
        for (int k16 = 0; k16 < 4; k16++) {
            const uint32_t aB = st + offA[k16];
            const uint32_t bB = st + offB[k16];
            uint32_t afr[2][4];
            ldmatrix_x4(afr[0], aB);
            ldmatrix_x4(afr[1], aB + 2048);
#pragma unroll
            for (int g = 0; g < 4; g++) {
                uint32_t bfr[4];
                ldmatrix_x4(bfr, bB + g * 2048);
#pragma unroll
                for (int mt = 0; mt < 2; mt++) {
#pragma unroll
                    for (int p = 0; p < 2; p++) {
                        mma16816(acc[mt][g * 2 + p], afr[mt], bfr[p], bfr[2 + p]);
                    }
                }
            }
        }
        cs = (cs + 1 == GSTAGES) ? 0 : cs + 1;
        ls = (ls + 1 == GSTAGES) ? 0 : ls + 1;
    }

    // ---------------- epilogue ----------------
    float mean = 0.f, invstd = 1.f;
    if (EPI == 0) { mean = g_stats[0]; invstd = g_stats[1]; }

    const int r_base = m0 + wm * 32 + (lane >> 2);
    const int c_base = n0 + wn * 64 + (lane & 3) * 2;

#pragma unroll
    for (int mt = 0; mt < 2; mt++) {
#pragma unroll
        for (int nf = 0; nf < 8; nf++) {
            const int col = c_base + nf * 8;
            float be0, be1;
            if (EPI == 0) {
                be0 = bias[col]     - mean * invstd * colsum[col];
                be1 = bias[col + 1] - mean * invstd * colsum[col + 1];
            } else {
                be0 = bias[col];
                be1 = bias[col + 1];
            }
#pragma unroll
            for (int hh = 0; hh < 2; hh++) {
                const int row = r_base + mt * 16 + hh * 8;
                float v0 = acc[mt][nf][hh * 2 + 0];
                float v1 = acc[mt][nf][hh * 2 + 1];
                if (EPI == 0) {
                    v0 = fast_tanh(fmaf(invstd, v0, be0));
                    v1 = fast_tanh(fmaf(invstd, v1, be1));
                } else {
                    v0 = fast_tanh(v0 + be0);
                    v1 = fast_tanh(v1 + be1);
                }
                __half2 hp = {__float2half_rn(v0), __float2half_rn(v1)};
                *(__half2*)(C + (size_t)row * Nout + col) = hp;
            }
        }
    }
}

// ---------------- spline (per-row block, 8 chunks) + colsum reset ----------
__global__ __launch_bounds__(256)
void spline_kernel(const __half* __restrict__ net, const float* __restrict__ x_in,
                   const float* __restrict__ logd, float* __restrict__ phi_out,
                   float* __restrict__ log_out) {
    const int b = blockIdx.x;
    const int tid = threadIdx.x;
    const __half* row = net + (size_t)b * OUTW;

    __shared__ float sh[256 * NC];
    __shared__ float red[256];

    if (b < 4) g_colsum[b * 256 + tid] = 0.f;

    float lsum = 0.f;

    for (int chunk = 0; chunk < 8; chunk++) {
        __syncthreads();
        const __half2* rowc = (const __half2*)(row + (size_t)chunk * 256 * NC);
        for (int i = tid; i < 128 * NC; i += 256) {
            float2 v = __half22float2(rowc[i]);
            sh[2 * i]     = v.x;
            sh[2 * i + 1] = v.y;
        }
        __syncthreads();

        const int s = chunk * 256 + tid;
        const float* p = sh + tid * NC;

        float hr[9], wr[8];
#pragma unroll
        for (int c = 0; c < 9; c++) hr[c] = p[c];
#pragma unroll
        for (int c = 0; c < 8; c++) wr[c] = p[9 + c];

        float m = wr[0];
#pragma unroll
        for (int c = 1; c < 8; c++) m = fmaxf(m, wr[c]);
        float wn[8];
        float wsum = 0.f;
#pragma unroll
        for (int c = 0; c < 8; c++) { wn[c] = __expf(wr[c] - m); wsum += wn[c]; }
        float winv = 1.0f / wsum;
#pragma unroll
        for (int c = 0; c < 8; c++) wn[c] *= winv;

        float eh[9];
#pragma unroll
        for (int c = 0; c < 9; c++) eh[c] = __expf(hr[c]);
        float denom = 0.f;
#pragma unroll
        for (int c = 0; c < 8; c++) denom += 0.5f * wn[c] * (eh[c] + eh[c + 1]);
        float dinv = 1.0f / denom;
        float hn[9];
#pragma unroll
        for (int c = 0; c < 9; c++) hn[c] = eh[c] * dinv;

        const float x = x_in[(size_t)b * SIZE_D + s] * 0.31830988618379067154f;

        float cum = 0.f, phicum = 0.f;
        float wk = wn[0], hk = hn[0], hk1 = hn[1];
        float xkm1 = -EPS_C, phikm1 = 0.f;
#pragma unroll
        for (int i = 0; i < 7; i++) {
            float trap = 0.5f * wn[i] * (hn[i] + hn[i + 1]);
            cum += wn[i];
            phicum += trap;
            bool c = (cum < x);
            wk     = c ? wn[i + 1] : wk;
            hk     = c ? hn[i + 1] : hk;
            hk1    = c ? hn[i + 2] : hk1;
            xkm1   = c ? cum      : xkm1;
            phikm1 = c ? phicum   : phikm1;
        }

        float alpha = (x - xkm1) / wk;
        float phi = phikm1 + alpha * hk * wk
                  + 0.5f * alpha * alpha * (hk1 - hk) * wk;
        phi_out[(size_t)b * SIZE_D + s] = phi;
        lsum += __logf(hk + alpha * (hk1 - hk));
    }

    red[tid] = lsum;
    __syncthreads();
    for (int o = 128; o > 0; o >>= 1) {
        if (tid < o) red[tid] += red[tid + o];
        __syncthreads();
    }
    if (tid == 0) log_out[b] = logd[b] - red[0];
}

// ---------------- launch ----------------
extern "C" void kernel_launch(void* const* d_in, const int* in_sizes, int n_in,
                              void* d_out, int out_size) {
    (void)in_sizes; (void)n_in; (void)out_size;
    const float* x_in      = (const float*)d_in[0];
    const float* x_passive = (const float*)d_in[1];
    const float* log_dens  = (const float*)d_in[2];
    const float* w1        = (const float*)d_in[3];
    const float* b1        = (const float*)d_in[4];
    const float* w2        = (const float*)d_in[5];
    const float* b2        = (const float*)d_in[6];

    float* out_phi = (float*)d_out;
    float* out_log = (float*)d_out + (size_t)NTOT;

    __half *xh, *w1t, *hbuf, *w2t, *nbuf;
    float *csum;
    cudaGetSymbolAddress((void**)&xh, g_xh);
    cudaGetSymbolAddress((void**)&w1t, g_w1t);
    cudaGetSymbolAddress((void**)&hbuf, g_h);
    cudaGetSymbolAddress((void**)&w2t, g_w2t);
    cudaGetSymbolAddress((void**)&nbuf, g_net);
    cudaGetSymbolAddress((void**)&csum, g_colsum);

    cudaFuncSetAttribute((const void*)gemm_fp16<0>,
                         cudaFuncAttributeMaxDynamicSharedMemorySize, GEMM_SMEM);
    cudaFuncSetAttribute((const void*)gemm_fp16<1>,
                         cudaFuncAttributeMaxDynamicSharedMemorySize, GEMM_SMEM);

    // 1) fused prep: stats(+finalize) + x fp16 + w1t(+colsum) + w2t
    prep_fused<<<NSTATBLK + NW1T + NW2T, 256>>>(x_passive, xh, w1, w1t, w2, w2t);
    // 2) GEMM1: h = tanh(xs @ w1 + b1) -> fp16   K=2048, KTILES=32
    gemm_fp16<0><<<dim3(BATCH / GBM, HID / 128), 256, GEMM_SMEM>>>(
        xh, w1t, b1, csum, hbuf, SIZE_D, HID, SIZE_D / GBK);
    // 3) GEMM2: net = tanh(h @ w2 + b2) -> fp16  K=1024, KTILES=16
    gemm_fp16<1><<<dim3(BATCH / GBM, OUTW / 128), 256, GEMM_SMEM>>>(
        hbuf, w2t, b2, nullptr, nbuf, HID, OUTW, HID / GBK);
    // 4) spline + per-row log reduction + colsum reset [ncu capture slot]
    spline_kernel<<<BATCH, 256>>>(nbuf, x_in, log_dens, out_phi, out_log);
}

// round 15
// speedup vs baseline: 1.2422x; 1.0497x over previous
#include <cuda_runtime.h>
#include <cuda_fp16.h>
#include <math.h>
#include <stdint.h>

// ---------------- problem constants ----------------
#define BATCH 2048
#define SIZE_D 2048
#define HID 1024
#define NC 17
#define OUTW (SIZE_D * NC)   // 34816
#define NTOT (BATCH * SIZE_D)
#define EPS_C 1e-6f
#define NSTATBLK (NTOT / 4 / 256)              // 4096
#define NW1T ((HID / 64) * (SIZE_D / 64))      // 512
#define NW2T ((OUTW / 64) * (HID / 64))        // 8704

// ---------------- GEMM tiling: 128x128 block, GBK=64 ----------------
#define GBM 128
#define GBK 64
#define GSTAGES 3
#define TILE_BYTES 16384                       // 128 rows x 128B
#define STAGE_B (2 * TILE_BYTES)               // 32768
#define GEMM_SMEM (GSTAGES * STAGE_B)          // 98304 -> 2 CTAs/SM

// spline chunk: 256 sites x 17 halfs = 8704 bytes = 544 x 16B
#define SCHUNK_B (256 * NC * 2)
#define SCHUNK_16 (SCHUNK_B / 16)              // 544

// ---------------- device scratch ----------------
__device__ __half g_xh[(size_t)NTOT];
__device__ __half g_w1t[(size_t)HID * SIZE_D];
__device__ __half g_h[(size_t)BATCH * HID];
__device__ __half g_w2t[(size_t)OUTW * HID];
__device__ __half g_net[(size_t)BATCH * OUTW];
__device__ float g_colsum[HID];          // zero at load; re-zeroed by spline
__device__ float g_part_s[NSTATBLK];
__device__ float g_part_ss[NSTATBLK];
__device__ float g_stats[2];
__device__ unsigned int g_ctr;

// ---------------- PTX helpers ----------------
__device__ __forceinline__ uint32_t smem_u32(const void* p) {
    uint32_t a;
    asm("{ .reg .u64 t; cvta.to.shared.u64 t, %1; cvt.u32.u64 %0, t; }"
        : "=r"(a) : "l"(p));
    return a;
}
__device__ __forceinline__ void cp_async16(uint32_t sa, const void* ga) {
    asm volatile("cp.async.cg.shared.global [%0], [%1], 16;"
                 :: "r"(sa), "l"(ga) : "memory");
}
__device__ __forceinline__ void cp_commit() {
    asm volatile("cp.async.commit_group;" ::: "memory");
}
template <int N>
__device__ __forceinline__ void cp_wait() {
    asm volatile("cp.async.wait_group %0;" :: "n"(N) : "memory");
}
__device__ __forceinline__ void ldmatrix_x4(uint32_t* r, uint32_t addr) {
    asm volatile("ldmatrix.sync.aligned.m8n8.x4.shared.b16 {%0,%1,%2,%3}, [%4];"
                 : "=r"(r[0]), "=r"(r[1]), "=r"(r[2]), "=r"(r[3])
                 : "r"(addr));
}
__device__ __forceinline__ void mma16816(float* c, const uint32_t* a,
                                         uint32_t b0, uint32_t b1) {
    asm volatile(
        "mma.sync.aligned.m16n8k16.row.col.f32.f16.f16.f32 "
        "{%0,%1,%2,%3}, {%4,%5,%6,%7}, {%8,%9}, {%0,%1,%2,%3};"
        : "+f"(c[0]), "+f"(c[1]), "+f"(c[2]), "+f"(c[3])
        : "r"(a[0]), "r"(a[1]), "r"(a[2]), "r"(a[3]), "r"(b0), "r"(b1));
}
// 128B-row swizzle: 16B chunk index XOR (row & 7)
__device__ __forceinline__ uint32_t sw128(int row, int ch) {
    return ((uint32_t)row << 7) + ((uint32_t)((ch ^ (row & 7)) & 7) << 4);
}
__device__ __forceinline__ float fast_tanh(float x) {
    float e = __expf(2.0f * x);
    return 1.0f - 2.0f / (e + 1.0f);
}

// ---------------- fused prep: stats + w1t + w2t ----------------
__device__ __forceinline__ void transpose_tile(
    const float* __restrict__ src, __half* __restrict__ dst,
    float* smembuf, int K, int N, int n0, int k0, int docolsum, int tid) {
    float (*t)[65] = (float (*)[65])smembuf;
    const int lr = tid >> 4;
    const int lc = (tid & 15) * 4;
#pragma unroll
    for (int i = 0; i < 64; i += 16) {
        float4 v = *(const float4*)(src + (size_t)(k0 + lr + i) * N + n0 + lc);
        t[lr + i][lc + 0] = v.x;
        t[lr + i][lc + 1] = v.y;
        t[lr + i][lc + 2] = v.z;
        t[lr + i][lc + 3] = v.w;
    }
    __syncthreads();
    if (docolsum && tid < 64) {
        float s = 0.f;
#pragma unroll
        for (int r = 0; r < 64; r++) s += t[r][tid];
        atomicAdd(&g_colsum[n0 + tid], s);
    }
    const int wid = tid >> 5;
    const int lane = tid & 31;
#pragma unroll
    for (int i = 0; i < 64; i += 8) {
        const int r = wid + i;
        const int k = lane * 2;
        __half2 hp = {__float2half_rn(t[k][r]), __float2half_rn(t[k + 1][r])};
        *(__half2*)(dst + (size_t)(n0 + r) * K + k0 + k) = hp;
    }
}

__global__ __launch_bounds__(256)
void prep_fused(const float* __restrict__ xp, __half* __restrict__ xh,
                const float* __restrict__ w1, __half* __restrict__ w1t,
                const float* __restrict__ w2, __half* __restrict__ w2t) {
    __shared__ float smembuf[64 * 65];
    __shared__ int slast;
    const int tid = threadIdx.x;

    if (blockIdx.x < NSTATBLK) {
        const int i = blockIdx.x * 256 + tid;
        float4 v = ((const float4*)xp)[i];

        __half2 p0 = {__float2half_rn(v.x), __float2half_rn(v.y)};
        __half2 p1 = {__float2half_rn(v.z), __float2half_rn(v.w)};
        uint2 hv = {*(uint32_t*)&p0, *(uint32_t*)&p1};
        ((uint2*)xh)[i] = hv;

        float* shs = smembuf;
        float* shss = smembuf + 256;
        float s = v.x + v.y + v.z + v.w;
        float ss = v.x * v.x + v.y * v.y + v.z * v.z + v.w * v.w;
        shs[tid] = s; shss[tid] = ss;
        __syncthreads();
        for (int o = 128; o > 0; o >>= 1) {
            if (tid < o) { shs[tid] += shs[tid + o]; shss[tid] += shss[tid + o]; }
            __syncthreads();
        }
        if (tid == 0) {
            g_part_s[blockIdx.x] = shs[0];
            g_part_ss[blockIdx.x] = shss[0];
            __threadfence();
            unsigned int old = atomicAdd(&g_ctr, 1u);
            slast = (old == NSTATBLK - 1) ? 1 : 0;
        }
        __syncthreads();
        if (slast) {
            __threadfence();
            float fs = 0.f, fss = 0.f;
            for (int k = tid; k < NSTATBLK; k += 256) {
                fs += g_part_s[k]; fss += g_part_ss[k];
            }
            shs[tid] = fs; shss[tid] = fss;
            __syncthreads();
            for (int o = 128; o > 0; o >>= 1) {
                if (tid < o) { shs[tid] += shs[tid + o]; shss[tid] += shss[tid + o]; }
                __syncthreads();
            }
            if (tid == 0) {
                float S = shs[0], SS = shss[0];
                float mean = S / (float)NTOT;
                float var = (SS - S * mean) / (float)(NTOT - 1);
                g_stats[0] = mean;
                g_stats[1] = rsqrtf(var);
                g_ctr = 0;
            }
        }
    } else if (blockIdx.x < NSTATBLK + NW1T) {
        const int bid = blockIdx.x - NSTATBLK;
        const int n0 = (bid & 15) * 64;
        const int k0 = (bid >> 4) * 64;
        transpose_tile(w1, w1t, smembuf, SIZE_D, HID, n0, k0, 1, tid);
    } else {
        const int bid = blockIdx.x - NSTATBLK - NW1T;
        const int n0 = (bid % (OUTW / 64)) * 64;
        const int k0 = (bid / (OUTW / 64)) * 64;
        transpose_tile(w2, w2t, smembuf, HID, OUTW, n0, k0, 0, tid);
    }
}

// ---------------- fp16 GEMM: 128x128 tile, GBK=64, delta-swizzled offsets ---
template <int EPI>
__global__ __launch_bounds__(256, 2)
void gemm_fp16(const __half* __restrict__ A,
               const __half* __restrict__ B,
               const float* __restrict__ bias,
               const float* __restrict__ colsum,
               __half* __restrict__ C,
               int K, int Nout, int KTILES) {
    extern __shared__ __align__(128) char smem[];
    const uint32_t sb = smem_u32(smem);
    const int tid = threadIdx.x;
    const int wid = tid >> 5;
    const int lane = tid & 31;
    const int wm = wid & 3;
    const int wn = wid >> 2;
    const int m0 = blockIdx.x * GBM;
    const int n0 = blockIdx.y * 128;

    const int rr = tid >> 3;
    const int cc = tid & 7;
    const uint32_t so = sw128(rr, cc);

    const __half* pA = A + (size_t)(m0 + rr) * K + cc * 8;
    const __half* pB = B + (size_t)(n0 + rr) * K + cc * 8;
    const size_t k32 = (size_t)32 * K;
    const size_t k64 = (size_t)64 * K;
    const size_t k96 = (size_t)96 * K;

    auto load_stage_at = [&](uint32_t base) {
        cp_async16(base + so,          pA);
        cp_async16(base + so + 4096,   pA + k32);
        cp_async16(base + so + 8192,   pA + k64);
        cp_async16(base + so + 12288,  pA + k96);
        const uint32_t bb = base + TILE_BYTES;
        cp_async16(bb + so,            pB);
        cp_async16(bb + so + 4096,     pB + k32);
        cp_async16(bb + so + 8192,     pB + k64);
        cp_async16(bb + so + 12288,    pB + k96);
        pA += GBK; pB += GBK;
    };

    const int lrow = lane & 15;
    const int lhalf = lane >> 4;
    uint32_t offA[4], offB[4];
#pragma unroll
    for (int k16 = 0; k16 < 4; k16++) {
        const int kc = k16 * 2 + lhalf;
        offA[k16] = sw128(wm * 32 + lrow, kc);
        offB[k16] = TILE_BYTES + sw128(wn * 64 + lrow, kc);
    }

    float acc[2][8][4];
#pragma unroll
    for (int a = 0; a < 2; a++)
#pragma unroll
        for (int b = 0; b < 8; b++)
#pragma unroll
            for (int c = 0; c < 4; c++) acc[a][b][c] = 0.f;

#pragma unroll
    for (int s = 0; s < GSTAGES - 1; s++) {
        load_stage_at(sb + s * STAGE_B);
        cp_commit();
    }

    int cs = 0;
    int ls = GSTAGES - 1;
    for (int kt = 0; kt < KTILES; kt++) {
        cp_wait<GSTAGES - 2>();
        __syncthreads();

        if (kt + GSTAGES - 1 < KTILES) load_stage_at(sb + ls * STAGE_B);
        cp_commit();

        const uint32_t st = sb + cs * STAGE_B;
#pragma unroll
        for (int k16 = 0; k16 < 4; k16++) {
            const uint32_t aB = st + offA[k16];
            const uint32_t bB = st + offB[k16];
            uint32_t afr[2][4];
            ldmatrix_x4(afr[0], aB);
            ldmatrix_x4(afr[1], aB + 2048);
#pragma unroll
            for (int g = 0; g < 4; g++) {
                uint32_t bfr[4];
                ldmatrix_x4(bfr, bB + g * 2048);
#pragma unroll
                for (int mt = 0; mt < 2; mt++) {
#pragma unroll
                    for (int p = 0; p < 2; p++) {
                        mma16816(acc[mt][g * 2 + p], afr[mt], bfr[p], bfr[2 + p]);
                    }
                }
            }
        }
        cs = (cs + 1 == GSTAGES) ? 0 : cs + 1;
        ls = (ls + 1 == GSTAGES) ? 0 : ls + 1;
    }

    float mean = 0.f, invstd = 1.f;
    if (EPI == 0) { mean = g_stats[0]; invstd = g_stats[1]; }

    const int r_base = m0 + wm * 32 + (lane >> 2);
    const int c_base = n0 + wn * 64 + (lane & 3) * 2;

#pragma unroll
    for (int mt = 0; mt < 2; mt++) {
#pragma unroll
        for (int nf = 0; nf < 8; nf++) {
            const int col = c_base + nf * 8;
            float be0, be1;
            if (EPI == 0) {
                be0 = bias[col]     - mean * invstd * colsum[col];
                be1 = bias[col + 1] - mean * invstd * colsum[col + 1];
            } else {
                be0 = bias[col];
                be1 = bias[col + 1];
            }
#pragma unroll
            for (int hh = 0; hh < 2; hh++) {
                const int row = r_base + mt * 16 + hh * 8;
                float v0 = acc[mt][nf][hh * 2 + 0];
                float v1 = acc[mt][nf][hh * 2 + 1];
                if (EPI == 0) {
                    v0 = fast_tanh(fmaf(invstd, v0, be0));
                    v1 = fast_tanh(fmaf(invstd, v1, be1));
                } else {
                    v0 = fast_tanh(v0 + be0);
                    v1 = fast_tanh(v1 + be1);
                }
                __half2 hp = {__float2half_rn(v0), __float2half_rn(v1)};
                *(__half2*)(C + (size_t)row * Nout + col) = hp;
            }
        }
    }
}

// ---------------- spline: cp.async double-buffered chunks ----------------
__global__ __launch_bounds__(256)
void spline_kernel(const __half* __restrict__ net, const float* __restrict__ x_in,
                   const float* __restrict__ logd, float* __restrict__ phi_out,
                   float* __restrict__ log_out) {
    const int b = blockIdx.x;
    const int tid = threadIdx.x;
    const char* row = (const char*)(net + (size_t)b * OUTW);

    __shared__ __align__(16) __half sh[2][256 * NC];   // 2 x 8704 B
    __shared__ float red[256];

    if (b < 4) g_colsum[b * 256 + tid] = 0.f;

    const uint32_t sbase0 = smem_u32(&sh[0][0]);
    const uint32_t sbase1 = smem_u32(&sh[1][0]);

    auto issue_chunk = [&](int buf, int chunk) {
        const uint32_t sb_ = buf ? sbase1 : sbase0;
        const char* src = row + (size_t)chunk * SCHUNK_B;
        cp_async16(sb_ + tid * 16, src + tid * 16);
        cp_async16(sb_ + (tid + 256) * 16, src + (size_t)(tid + 256) * 16);
        if (tid < SCHUNK_16 - 512)
            cp_async16(sb_ + (tid + 512) * 16, src + (size_t)(tid + 512) * 16);
        cp_commit();
    };

    issue_chunk(0, 0);

    float lsum = 0.f;

    for (int chunk = 0; chunk < 8; chunk++) {
        cp_wait<0>();
        __syncthreads();   // chunk data visible; all threads done with prev buf

        if (chunk < 7) issue_chunk((chunk + 1) & 1, chunk + 1);

        const __half* p = &sh[chunk & 1][tid * NC];

        float hr[9], wr[8];
#pragma unroll
        for (int c = 0; c < 9; c++) hr[c] = __half2float(p[c]);
#pragma unroll
        for (int c = 0; c < 8; c++) wr[c] = __half2float(p[9 + c]);

        float m = wr[0];
#pragma unroll
        for (int c = 1; c < 8; c++) m = fmaxf(m, wr[c]);
        float wn[8];
        float wsum = 0.f;
#pragma unroll
        for (int c = 0; c < 8; c++) { wn[c] = __expf(wr[c] - m); wsum += wn[c]; }
        float winv = 1.0f / wsum;
#pragma unroll
        for (int c = 0; c < 8; c++) wn[c] *= winv;

        float eh[9];
#pragma unroll
        for (int c = 0; c < 9; c++) eh[c] = __expf(hr[c]);
        float denom = 0.f;
#pragma unroll
        for (int c = 0; c < 8; c++) denom += 0.5f * wn[c] * (eh[c] + eh[c + 1]);
        float dinv = 1.0f / denom;
        float hn[9];
#pragma unroll
        for (int c = 0; c < 9; c++) hn[c] = eh[c] * dinv;

        const int s = chunk * 256 + tid;
        const float x = x_in[(size_t)b * SIZE_D + s] * 0.31830988618379067154f;

        float cum = 0.f, phicum = 0.f;
        float wk = wn[0], hk = hn[0], hk1 = hn[1];
        float xkm1 = -EPS_C, phikm1 = 0.f;
#pragma unroll
        for (int i = 0; i < 7; i++) {
            float trap = 0.5f * wn[i] * (hn[i] + hn[i + 1]);
            cum += wn[i];
            phicum += trap;
            bool c = (cum < x);
            wk     = c ? wn[i + 1] : wk;
            hk     = c ? hn[i + 1] : hk;
            hk1    = c ? hn[i + 2] : hk1;
            xkm1   = c ? cum      : xkm1;
            phikm1 = c ? phicum   : phikm1;
        }

        float alpha = (x - xkm1) / wk;
        float phi = phikm1 + alpha * hk * wk
                  + 0.5f * alpha * alpha * (hk1 - hk) * wk;
        phi_out[(size_t)b * SIZE_D + s] = phi;
        lsum += __logf(hk + alpha * (hk1 - hk));
    }

    red[tid] = lsum;
    __syncthreads();
    for (int o = 128; o > 0; o >>= 1) {
        if (tid < o) red[tid] += red[tid + o];
        __syncthreads();
    }
    if (tid == 0) log_out[b] = logd[b] - red[0];
}

// ---------------- launch ----------------
extern "C" void kernel_launch(void* const* d_in, const int* in_sizes, int n_in,
                              void* d_out, int out_size) {
    (void)in_sizes; (void)n_in; (void)out_size;
    const float* x_in      = (const float*)d_in[0];
    const float* x_passive = (const float*)d_in[1];
    const float* log_dens  = (const float*)d_in[2];
    const float* w1        = (const float*)d_in[3];
    const float* b1        = (const float*)d_in[4];
    const float* w2        = (const float*)d_in[5];
    const float* b2        = (const float*)d_in[6];

    float* out_phi = (float*)d_out;
    float* out_log = (float*)d_out + (size_t)NTOT;

    __half *xh, *w1t, *hbuf, *w2t, *nbuf;
    float *csum;
    cudaGetSymbolAddress((void**)&xh, g_xh);
    cudaGetSymbolAddress((void**)&w1t, g_w1t);
    cudaGetSymbolAddress((void**)&hbuf, g_h);
    cudaGetSymbolAddress((void**)&w2t, g_w2t);
    cudaGetSymbolAddress((void**)&nbuf, g_net);
    cudaGetSymbolAddress((void**)&csum, g_colsum);

    cudaFuncSetAttribute((const void*)gemm_fp16<0>,
                         cudaFuncAttributeMaxDynamicSharedMemorySize, GEMM_SMEM);
    cudaFuncSetAttribute((const void*)gemm_fp16<1>,
                         cudaFuncAttributeMaxDynamicSharedMemorySize, GEMM_SMEM);

    // 1) fused prep: stats(+finalize) + x fp16 + w1t(+colsum) + w2t
    prep_fused<<<NSTATBLK + NW1T + NW2T, 256>>>(x_passive, xh, w1, w1t, w2, w2t);
    // 2) GEMM1: h = tanh(xs @ w1 + b1) -> fp16   K=2048, KTILES=32
    gemm_fp16<0><<<dim3(BATCH / GBM, HID / 128), 256, GEMM_SMEM>>>(
        xh, w1t, b1, csum, hbuf, SIZE_D, HID, SIZE_D / GBK);
    // 3) GEMM2: net = tanh(h @ w2 + b2) -> fp16  K=1024, KTILES=16
    gemm_fp16<1><<<dim3(BATCH / GBM, OUTW / 128), 256, GEMM_SMEM>>>(
        hbuf, w2t, b2, nullptr, nbuf, HID, OUTW, HID / GBK);
    // 4) spline: cp.async double-buffered + per-row log reduction
    spline_kernel<<<BATCH, 256>>>(nbuf, x_in, log_dens, out_phi, out_log);
}